// round 7
// baseline (speedup 1.0000x reference)
#include <cuda_runtime.h>
#include <cuda_bf16.h>
#include <cstdint>

#define NG 8
#define NE 8192
#define NN 512
#define NP1 513
#define HH 32
#define PLANE (513*513)

#define STAGE_F4 1792   // float4 chunks per stage: angle 896 + dists 896
#define NSTAGE 4        // 512 j-points / 128 per stage

// ---------------------------------------------------------------------------
// helpers
// ---------------------------------------------------------------------------
__device__ __forceinline__ unsigned packbf(float lo, float hi) {
    __nv_bfloat162 t = __floats2bfloat162_rn(lo, hi);
    return *reinterpret_cast<unsigned*>(&t);
}

__device__ __forceinline__ void mma_bf16(float* c, const unsigned* a, uint2 b) {
    asm volatile(
        "mma.sync.aligned.m16n8k16.row.col.f32.bf16.bf16.f32 "
        "{%0,%1,%2,%3}, {%4,%5,%6,%7}, {%8,%9}, {%0,%1,%2,%3};\n"
        : "+f"(c[0]), "+f"(c[1]), "+f"(c[2]), "+f"(c[3])
        : "r"(a[0]), "r"(a[1]), "r"(a[2]), "r"(a[3]), "r"(b.x), "r"(b.y));
}

__device__ __forceinline__ void cp16(void* smem_dst, const void* gsrc) {
    uint32_t a = (uint32_t)__cvta_generic_to_shared(smem_dst);
    asm volatile("cp.async.cg.shared.global [%0], [%1], 16;" :: "r"(a), "l"(gsrc));
}
__device__ __forceinline__ void cp_commit() {
    asm volatile("cp.async.commit_group;" ::: "memory");
}
template <int N>
__device__ __forceinline__ void cp_wait() {
    asm volatile("cp.async.wait_group %0;" :: "n"(N) : "memory");
}

// ---------------------------------------------------------------------------
// Kernel A: interior fill  out[g,h,i,j] for i,j in [1,512]
// block = 256 threads (8 warps) per (g,i) row. Inputs staged via a 2-deep
// cp.async pipeline (coalesced 16B chunks); MLPs via bf16 mma.sync; weight
// fragments in lane-major SMEM so regs stay low (2 CTAs/SM).
// ---------------------------------------------------------------------------
__global__ __launch_bounds__(256, 2) void interior_kernel(
    const float* __restrict__ attn_bias,
    const float* __restrict__ angle,
    const float* __restrict__ dists,
    const float* __restrict__ ang_w1, const float* __restrict__ ang_b1,
    const float* __restrict__ ang_w2, const float* __restrict__ ang_b2,
    const float* __restrict__ md_w1,  const float* __restrict__ md_b1,
    const float* __restrict__ md_w2,  const float* __restrict__ md_b2,
    float* __restrict__ out)
{
    __shared__ float4 stage[2][STAGE_F4];       // [buf][angle 896 | dists 896]
    __shared__ uint2  wfrag[32][32];            // [m*8+s*4+n][lane] B-frag
    __shared__ float2 bfr[3][4][32];            // [mat][n][lane] bias pairs

    const int tid = threadIdx.x;

    // ---- build weight/bias fragments (weights are tiny; L2-resident) ----
    for (int e = tid; e < 1024; e += 256) {
        const int p = e >> 5, ln = e & 31;
        const int m = p >> 3, s = (p >> 2) & 1, n = p & 3;
        const int q = ln >> 2, tq4 = ln & 3;
        const int r0 = s * 16 + tq4 * 2;
        const int c  = n * 8 + q;
        const float* w = (m == 0) ? ang_w1 : (m == 1) ? md_w1 : (m == 2) ? ang_w2 : md_w2;
        const bool pad = (m < 2);   // w1 matrices: rows 28..31 are zero
        float v00 = (pad && r0     >= 28) ? 0.f : w[(r0)     * 32 + c];
        float v01 = (pad && r0 + 1 >= 28) ? 0.f : w[(r0 + 1) * 32 + c];
        float v10 = (pad && r0 + 8 >= 28) ? 0.f : w[(r0 + 8) * 32 + c];
        float v11 = (pad && r0 + 9 >= 28) ? 0.f : w[(r0 + 9) * 32 + c];
        wfrag[p][ln] = make_uint2(packbf(v00, v01), packbf(v10, v11));
    }
    for (int e = tid; e < 384; e += 256) {
        const int mat = e >> 7, rem = e & 127, n = rem >> 5, ln = rem & 31;
        const int i2 = n * 8 + (ln & 3) * 2;
        float lo, hi;
        if (mat == 0)      { lo = ang_b1[i2];              hi = ang_b1[i2 + 1]; }
        else if (mat == 1) { lo = md_b1[i2];               hi = md_b1[i2 + 1]; }
        else               { lo = ang_b2[i2] + md_b2[i2];  hi = ang_b2[i2 + 1] + md_b2[i2 + 1]; }
        bfr[mat][n][ln] = make_float2(lo, hi);
    }

    const int bid = blockIdx.x;
    const int g = bid >> 9;           // / 512
    const int i = (bid & 511) + 1;    // out row 1..512
    const size_t rowp = (size_t)(g * NN + (i - 1)) * NN * 28;   // 112B-aligned
    const float4* angR = (const float4*)(angle + rowp);
    const float4* dstR = (const float4*)(dists + rowp);
    const float* attnRow = attn_bias + ((size_t)g * NP1 + i) * NP1;
    float* outRow = out + (size_t)g * HH * PLANE + (size_t)i * NP1;

    const int lane = tid & 31;
    const int warp = tid >> 5;
    const int qid  = lane >> 2;   // 0..7
    const int tq   = lane & 3;    // 0..3

    // ---- pipeline fill stage: coalesced 16B cp.async chunks ----
    // stage s covers j in [s*128, s*128+128): angle float4 [s*896, s*896+896)
    #define ISSUE_STAGE(s, b)                                                 \
        {                                                                     \
            const float4* a4 = angR + (s) * 896;                              \
            const float4* d4 = dstR + (s) * 896;                              \
            _Pragma("unroll")                                                 \
            for (int it = 0; it < 7; it++) {                                  \
                const int k = tid + it * 256;                                 \
                const float4* src = (k < 896) ? (a4 + k) : (d4 + (k - 896));  \
                cp16(&stage[b][k], src);                                      \
            }                                                                 \
            cp_commit();                                                      \
        }

    ISSUE_STAGE(0, 0);
    ISSUE_STAGE(1, 1);

    const int k0 = tq * 2;        // layer-1 kstep-0 cols
    const int k1 = 16 + tq * 2;   // layer-1 kstep-1 cols (k1+8 valid iff tq<2)

#pragma unroll
    for (int s = 0; s < NSTAGE; s++) {
        const int b = s & 1;
        if (s < NSTAGE - 1) cp_wait<1>(); else cp_wait<0>();
        __syncthreads();

        // ---- consume: this warp's 16-point tile ----
        const int j0 = s * 128 + warp * 16;
        const float* aS = (const float*)stage[b];          // 128 rows x 28 f
        const float* dS = aS + 896 * 4;
        const int r0 = (warp * 16 + qid) * 28;
        const int r1 = r0 + 8 * 28;

        const float at0 = __ldg(attnRow + j0 + 1 + qid);
        const float at1 = __ldg(attnRow + j0 + 9 + qid);

        float c2[4][4];
#pragma unroll
        for (int n = 0; n < 4; n++) {
            const float2 bb = bfr[2][n][lane];
            c2[n][0] = bb.x; c2[n][1] = bb.y; c2[n][2] = bb.x; c2[n][3] = bb.y;
        }

        float hh[4][4];
        unsigned A[4];

        // ---- MLP(angle), layer 1 ----
#pragma unroll
        for (int n = 0; n < 4; n++) {
            const float2 bb = bfr[0][n][lane];
            hh[n][0] = bb.x; hh[n][1] = bb.y; hh[n][2] = bb.x; hh[n][3] = bb.y;
        }
        {
            float2 x0 = *(const float2*)(aS + r0 + k0);
            float2 x1 = *(const float2*)(aS + r1 + k0);
            float2 x2 = *(const float2*)(aS + r0 + k0 + 8);
            float2 x3 = *(const float2*)(aS + r1 + k0 + 8);
            A[0] = packbf(x0.x, x0.y); A[1] = packbf(x1.x, x1.y);
            A[2] = packbf(x2.x, x2.y); A[3] = packbf(x3.x, x3.y);
#pragma unroll
            for (int n = 0; n < 4; n++) mma_bf16(hh[n], A, wfrag[0 + n][lane]);
            x0 = *(const float2*)(aS + r0 + k1);
            x1 = *(const float2*)(aS + r1 + k1);
            if (tq < 2) {
                x2 = *(const float2*)(aS + r0 + k1 + 8);
                x3 = *(const float2*)(aS + r1 + k1 + 8);
            } else { x2 = make_float2(0.f, 0.f); x3 = make_float2(0.f, 0.f); }
            A[0] = packbf(x0.x, x0.y); A[1] = packbf(x1.x, x1.y);
            A[2] = packbf(x2.x, x2.y); A[3] = packbf(x3.x, x3.y);
#pragma unroll
            for (int n = 0; n < 4; n++) mma_bf16(hh[n], A, wfrag[4 + n][lane]);
        }
        // relu -> layer 2 (ang_w2 = matrix 2)
#pragma unroll
        for (int ss = 0; ss < 2; ss++) {
            A[0] = packbf(fmaxf(hh[2*ss][0], 0.f), fmaxf(hh[2*ss][1], 0.f));
            A[1] = packbf(fmaxf(hh[2*ss][2], 0.f), fmaxf(hh[2*ss][3], 0.f));
            A[2] = packbf(fmaxf(hh[2*ss+1][0], 0.f), fmaxf(hh[2*ss+1][1], 0.f));
            A[3] = packbf(fmaxf(hh[2*ss+1][2], 0.f), fmaxf(hh[2*ss+1][3], 0.f));
#pragma unroll
            for (int n = 0; n < 4; n++) mma_bf16(c2[n], A, wfrag[16 + ss * 4 + n][lane]);
        }

        // ---- MLP(dists), layer 1 ----
#pragma unroll
        for (int n = 0; n < 4; n++) {
            const float2 bb = bfr[1][n][lane];
            hh[n][0] = bb.x; hh[n][1] = bb.y; hh[n][2] = bb.x; hh[n][3] = bb.y;
        }
        {
            float2 x0 = *(const float2*)(dS + r0 + k0);
            float2 x1 = *(const float2*)(dS + r1 + k0);
            float2 x2 = *(const float2*)(dS + r0 + k0 + 8);
            float2 x3 = *(const float2*)(dS + r1 + k0 + 8);
            A[0] = packbf(x0.x, x0.y); A[1] = packbf(x1.x, x1.y);
            A[2] = packbf(x2.x, x2.y); A[3] = packbf(x3.x, x3.y);
#pragma unroll
            for (int n = 0; n < 4; n++) mma_bf16(hh[n], A, wfrag[8 + n][lane]);
            x0 = *(const float2*)(dS + r0 + k1);
            x1 = *(const float2*)(dS + r1 + k1);
            if (tq < 2) {
                x2 = *(const float2*)(dS + r0 + k1 + 8);
                x3 = *(const float2*)(dS + r1 + k1 + 8);
            } else { x2 = make_float2(0.f, 0.f); x3 = make_float2(0.f, 0.f); }
            A[0] = packbf(x0.x, x0.y); A[1] = packbf(x1.x, x1.y);
            A[2] = packbf(x2.x, x2.y); A[3] = packbf(x3.x, x3.y);
#pragma unroll
            for (int n = 0; n < 4; n++) mma_bf16(hh[n], A, wfrag[12 + n][lane]);
        }
        // relu -> layer 2 (md_w2 = matrix 3)
#pragma unroll
        for (int ss = 0; ss < 2; ss++) {
            A[0] = packbf(fmaxf(hh[2*ss][0], 0.f), fmaxf(hh[2*ss][1], 0.f));
            A[1] = packbf(fmaxf(hh[2*ss][2], 0.f), fmaxf(hh[2*ss][3], 0.f));
            A[2] = packbf(fmaxf(hh[2*ss+1][0], 0.f), fmaxf(hh[2*ss+1][1], 0.f));
            A[3] = packbf(fmaxf(hh[2*ss+1][2], 0.f), fmaxf(hh[2*ss+1][3], 0.f));
#pragma unroll
            for (int n = 0; n < 4; n++) mma_bf16(c2[n], A, wfrag[24 + ss * 4 + n][lane]);
        }

        // ---- add attn_bias base, store ----
#pragma unroll
        for (int n = 0; n < 4; n++) {
            float* o = outRow + (size_t)(n * 8 + tq * 2) * PLANE;
            o[j0 + 1 + qid]         = c2[n][0] + at0;
            o[PLANE + j0 + 1 + qid] = c2[n][1] + at0;
            o[j0 + 9 + qid]         = c2[n][2] + at1;
            o[PLANE + j0 + 9 + qid] = c2[n][3] + at1;
        }

        __syncthreads();   // all warps done reading stage[b] before refill
        if (s < NSTAGE - 2) ISSUE_STAGE(s + 2, b);
    }
    #undef ISSUE_STAGE
}

// ---------------------------------------------------------------------------
// Kernel B: border fill (row 0 and column 0): attn + virt
// ---------------------------------------------------------------------------
__global__ __launch_bounds__(256) void border_kernel(
    const float* __restrict__ attn_bias,
    const float* __restrict__ virt,
    float* __restrict__ out)
{
    const int idx = blockIdx.x * 256 + threadIdx.x;
    const int total = NG * HH * 1025;
    if (idx >= total) return;
    const int pos = idx % 1025;
    const int gh  = idx / 1025;
    const int h = gh & 31;
    const int g = gh >> 5;
    const float v = virt[h];
    float* ob = out + ((size_t)(g * HH + h)) * PLANE;
    const float* ab = attn_bias + (size_t)g * PLANE;
    if (pos < NP1) {
        ob[pos] = ab[pos] + v;                        // row 0, all j
    } else {
        const int i = pos - 512;                      // 1..512
        ob[(size_t)i * NP1] = ab[(size_t)i * NP1] + v; // col 0
    }
}

// ---------------------------------------------------------------------------
// Kernel C: edge scatter-add. One warp per edge, lane = head h.
// edge_mask is a jax bool materialized as int32 by the harness.
// ---------------------------------------------------------------------------
__global__ __launch_bounds__(256) void edge_kernel(
    const float* __restrict__ edge_feat,
    const int*   __restrict__ edge_index,
    const int*   __restrict__ edge_mask,
    const int*   __restrict__ num_ligand_atoms,
    const float* __restrict__ struct_emb,
    const float* __restrict__ plip_lig,
    const float* __restrict__ plip_prot,
    const float* __restrict__ plip_inter,
    const float* __restrict__ dist_w1, const float* __restrict__ dist_b1,
    const float* __restrict__ dist_w2, const float* __restrict__ dist_b2,
    float* __restrict__ out)
{
    __shared__ float s_w2[1024];
    __shared__ float s_w1[32], s_b1[32], s_b2[32];
    const int tid = threadIdx.x;
    for (int idx = tid; idx < 1024; idx += 256) s_w2[idx] = dist_w2[idx];
    if (tid < 32) {
        s_w1[tid] = dist_w1[tid];
        s_b1[tid] = dist_b1[tid];
        s_b2[tid] = dist_b2[tid];
    }
    __syncthreads();

    const int warp = tid >> 5;
    const int lane = tid & 31;
    const int eid = blockIdx.x * 8 + warp;     // 0 .. G*E-1 (grid exact)
    if (eid >= NG * NE) return;
    if (edge_mask[eid] == 0) return;           // masked edges contribute 0

    const int g = eid >> 13;                   // / 8192
    const int e = eid & (NE - 1);

    const float4 ef = reinterpret_cast<const float4*>(edge_feat)[eid];
    const int t0 = (int)ef.x;
    const int t1 = (int)ef.y;
    const int t2 = (int)ef.z;
    const float d = ef.w;

    const int src = edge_index[(size_t)g * 2 * NE + e];
    const int tgt = edge_index[(size_t)g * 2 * NE + NE + e];
    int nl = num_ligand_atoms[g];
    nl = nl > 1 ? nl : 1;
    const bool sl = (src > 0) && (src < nl);
    const bool tl = (tgt > 0) && (tgt < nl);

    // distance MLP: scalar -> 32 -> 32 (lane = output h)
    const float hid = fmaxf(fmaf(d, s_w1[lane], s_b1[lane]), 0.f);
    float y = s_b2[lane];
#pragma unroll
    for (int m = 0; m < 32; m++)
        y = fmaf(__shfl_sync(0xffffffffu, hid, m), s_w2[m * 32 + lane], y);

    float sel = 0.f;
    if (t0 <= 1) {
        int si = t0 * 4 + t1 * 2 + t2;
        si = si < 0 ? 0 : (si > 19 ? 19 : si);
        sel = struct_emb[si * 32 + lane];
    } else if (t0 == 5) {
        int pi = t1 < 0 ? 0 : (t1 > 14 ? 14 : t1);
        const float* tab = (sl && tl) ? plip_lig : ((!sl && !tl) ? plip_prot : plip_inter);
        sel = tab[pi * 32 + lane];
    }

    atomicAdd(out + (((size_t)(g * HH + lane)) * NP1 + (src + 1)) * NP1 + (tgt + 1), y + sel);
}

// ---------------------------------------------------------------------------
extern "C" void kernel_launch(void* const* d_in, const int* in_sizes, int n_in,
                              void* d_out, int out_size) {
    const float* edge_feat  = (const float*)d_in[0];
    const int*   edge_index = (const int*)d_in[1];
    const int*   edge_mask  = (const int*)d_in[2];
    const int*   num_lig    = (const int*)d_in[3];
    const float* attn_bias  = (const float*)d_in[4];
    const float* angle      = (const float*)d_in[5];
    const float* dists      = (const float*)d_in[6];
    // d_in[7] node_feat unused (shape only in reference)
    const float* struct_emb = (const float*)d_in[8];
    const float* plip_lig   = (const float*)d_in[9];
    const float* plip_prot  = (const float*)d_in[10];
    const float* plip_inter = (const float*)d_in[11];
    const float* dist_w1 = (const float*)d_in[12];
    const float* dist_b1 = (const float*)d_in[13];
    const float* dist_w2 = (const float*)d_in[14];
    const float* dist_b2 = (const float*)d_in[15];
    const float* ang_w1  = (const float*)d_in[16];
    const float* ang_b1  = (const float*)d_in[17];
    const float* ang_w2  = (const float*)d_in[18];
    const float* ang_b2  = (const float*)d_in[19];
    const float* md_w1   = (const float*)d_in[20];
    const float* md_b1   = (const float*)d_in[21];
    const float* md_w2   = (const float*)d_in[22];
    const float* md_b2   = (const float*)d_in[23];
    const float* virt    = (const float*)d_in[24];
    float* out = (float*)d_out;

    // interior + border overwrite the whole output (disjoint regions),
    // then edge kernel atomically adds on top (stream-ordered).
    interior_kernel<<<NG * NN, 256>>>(attn_bias, angle, dists,
                                      ang_w1, ang_b1, ang_w2, ang_b2,
                                      md_w1, md_b1, md_w2, md_b2, out);
    border_kernel<<<(NG * HH * 1025 + 255) / 256, 256>>>(attn_bias, virt, out);
    edge_kernel<<<NG * NE / 8, 256>>>(edge_feat, edge_index, edge_mask, num_lig,
                                      struct_emb, plip_lig, plip_prot, plip_inter,
                                      dist_w1, dist_b1, dist_w2, dist_b2, out);
}

// round 8
// speedup vs baseline: 1.2420x; 1.2420x over previous
#include <cuda_runtime.h>
#include <cuda_bf16.h>
#include <cstdint>

#define NG 8
#define NE 8192
#define NN 512
#define NP1 513
#define HH 32
#define PLANE (513*513)

// ---------------------------------------------------------------------------
// helpers
// ---------------------------------------------------------------------------
__device__ __forceinline__ unsigned packbf(float lo, float hi) {
    __nv_bfloat162 t = __floats2bfloat162_rn(lo, hi);
    return *reinterpret_cast<unsigned*>(&t);
}
__device__ __forceinline__ unsigned packbf2(float2 v) { return packbf(v.x, v.y); }

__device__ __forceinline__ void mma_bf16(float* c, const unsigned* a, uint2 b) {
    asm volatile(
        "mma.sync.aligned.m16n8k16.row.col.f32.bf16.bf16.f32 "
        "{%0,%1,%2,%3}, {%4,%5,%6,%7}, {%8,%9}, {%0,%1,%2,%3};\n"
        : "+f"(c[0]), "+f"(c[1]), "+f"(c[2]), "+f"(c[3])
        : "r"(a[0]), "r"(a[1]), "r"(a[2]), "r"(a[3]), "r"(b.x), "r"(b.y));
}

__device__ __forceinline__ void ldm4(unsigned* r, uint32_t addr) {
    asm volatile("ldmatrix.sync.aligned.m8n8.x4.shared.b16 {%0,%1,%2,%3}, [%4];"
                 : "=r"(r[0]), "=r"(r[1]), "=r"(r[2]), "=r"(r[3]) : "r"(addr));
}

// ---------------------------------------------------------------------------
// Kernel A: interior fill  out[g,h,i,j] for i,j in [1,512]
// block = 256 threads (8 warps) per (g,i) row; warp-private pipeline:
//   coalesced LDG.64 fp32 -> regs -> bf16 STS into ldmatrix-layout smem
//   (80B row stride = conflict-free) -> ldmatrix.x4 A-frags -> mma.
// Weight/bias fragments in lane-major smem; 2 CTAs/SM.
// ---------------------------------------------------------------------------
__global__ __launch_bounds__(256, 2) void interior_kernel(
    const float* __restrict__ attn_bias,
    const float* __restrict__ angle,
    const float* __restrict__ dists,
    const float* __restrict__ ang_w1, const float* __restrict__ ang_b1,
    const float* __restrict__ ang_w2, const float* __restrict__ ang_b2,
    const float* __restrict__ md_w1,  const float* __restrict__ md_b1,
    const float* __restrict__ md_w2,  const float* __restrict__ md_b2,
    float* __restrict__ out)
{
    __shared__ uint2  wfrag[32][32];                       // [m*8+s*4+n][lane]
    __shared__ float2 bfr[3][4][32];                       // [mat][n][lane]
    __shared__ __align__(128) unsigned char mbuf[8][2560]; // per-warp: ang 16x80B | dst 16x80B

    const int tid = threadIdx.x;

    // ---- build weight/bias fragments (weights tiny; L2-resident) ----
    for (int e = tid; e < 1024; e += 256) {
        const int p = e >> 5, ln = e & 31;
        const int m = p >> 3, s = (p >> 2) & 1, n = p & 3;
        const int q = ln >> 2, tq4 = ln & 3;
        const int r0 = s * 16 + tq4 * 2;
        const int c  = n * 8 + q;
        const float* w = (m == 0) ? ang_w1 : (m == 1) ? md_w1 : (m == 2) ? ang_w2 : md_w2;
        const bool pad = (m < 2);   // w1 matrices: rows 28..31 are zero
        float v00 = (pad && r0     >= 28) ? 0.f : w[(r0)     * 32 + c];
        float v01 = (pad && r0 + 1 >= 28) ? 0.f : w[(r0 + 1) * 32 + c];
        float v10 = (pad && r0 + 8 >= 28) ? 0.f : w[(r0 + 8) * 32 + c];
        float v11 = (pad && r0 + 9 >= 28) ? 0.f : w[(r0 + 9) * 32 + c];
        wfrag[p][ln] = make_uint2(packbf(v00, v01), packbf(v10, v11));
    }
    for (int e = tid; e < 384; e += 256) {
        const int mat = e >> 7, rem = e & 127, n = rem >> 5, ln = rem & 31;
        const int i2 = n * 8 + (ln & 3) * 2;
        float lo, hi;
        if (mat == 0)      { lo = ang_b1[i2];              hi = ang_b1[i2 + 1]; }
        else if (mat == 1) { lo = md_b1[i2];               hi = md_b1[i2 + 1]; }
        else               { lo = ang_b2[i2] + md_b2[i2];  hi = ang_b2[i2 + 1] + md_b2[i2 + 1]; }
        bfr[mat][n][ln] = make_float2(lo, hi);
    }
    // zero the k=28..31 pad (bytes 56..63 of each of the 32 rows per warp buf);
    // converter only ever writes bytes 0..55, so this stays zero.
    *(float2*)(mbuf[tid >> 5] + (tid & 31) * 80 + 56) = make_float2(0.f, 0.f);
    __syncthreads();

    const int lane = tid & 31;
    const int warp = tid >> 5;
    const int qid  = lane >> 2;   // 0..7
    const int tq   = lane & 3;    // 0..3

    const int bid = blockIdx.x;
    const int g = bid >> 9;           // / 512
    const int i = (bid & 511) + 1;    // out row 1..512
    const size_t rowp = (size_t)(g * NN + (i - 1)) * NN * 28;
    const float* angRow  = angle + rowp;
    const float* dstRow  = dists + rowp;
    const float* attnRow = attn_bias + ((size_t)g * NP1 + i) * NP1;
    float* outRow = out + (size_t)g * HH * PLANE + (size_t)i * NP1;

    const uint32_t abase = (uint32_t)__cvta_generic_to_shared(mbuf[warp]);
    const uint32_t dbase = abase + 1280;
    const uint32_t lm_off = (uint32_t)((lane & 15) * 80 + ((lane >> 4) << 4));

    // ---- raw prefetch buffer (tile inputs as fp32 pairs, coalesced) ----
    float2 ra[7], rd[7];
    float at0, at1;
    {
        const float2* a2 = (const float2*)angRow + (size_t)(warp * 16) * 14;
        const float2* d2 = (const float2*)dstRow + (size_t)(warp * 16) * 14;
#pragma unroll
        for (int k = 0; k < 7; k++) {
            ra[k] = __ldcs(a2 + lane + 32 * k);
            rd[k] = __ldcs(d2 + lane + 32 * k);
        }
        at0 = __ldg(attnRow + warp * 16 + 1 + qid);
        at1 = __ldg(attnRow + warp * 16 + 9 + qid);
    }

#pragma unroll
    for (int it = 0; it < 4; it++) {
        const int t  = warp + it * 8;
        const int j0 = t * 16;

        // ---- convert + stage into warp-private ldmatrix buffer ----
        __syncwarp();   // WAR: prior ldmatrix reads must complete before overwrite
#pragma unroll
        for (int k = 0; k < 7; k++) {
            const int f   = lane + 32 * k;     // f2 index in tile (0..223)
            const int row = f / 14;
            const int c   = f - row * 14;
            const int off = row * 80 + c * 4;
            *(unsigned*)(mbuf[warp] + off)        = packbf2(ra[k]);
            *(unsigned*)(mbuf[warp] + 1280 + off) = packbf2(rd[k]);
        }
        __syncwarp();

        // ---- A fragments via ldmatrix (order matches mma mapping) ----
        unsigned Aa0[4], Aa1[4], Ad0[4], Ad1[4];
        ldm4(Aa0, abase + lm_off);        // angle k 0..15
        ldm4(Aa1, abase + lm_off + 32);   // angle k 16..31 (28..31 zero)
        ldm4(Ad0, dbase + lm_off);
        ldm4(Ad1, dbase + lm_off + 32);

        const float cat0 = at0, cat1 = at1;

        // ---- prefetch next tile (loads in flight during mma/store phase) ----
        if (it < 3) {
            const int jn = (t + 8) * 16;
            const float2* a2 = (const float2*)angRow + (size_t)jn * 14;
            const float2* d2 = (const float2*)dstRow + (size_t)jn * 14;
#pragma unroll
            for (int k = 0; k < 7; k++) {
                ra[k] = __ldcs(a2 + lane + 32 * k);
                rd[k] = __ldcs(d2 + lane + 32 * k);
            }
            at0 = __ldg(attnRow + jn + 1 + qid);
            at1 = __ldg(attnRow + jn + 9 + qid);
        }

        // ---- MLPs ----
        float c2[4][4];
#pragma unroll
        for (int n = 0; n < 4; n++) {
            const float2 bb = bfr[2][n][lane];
            c2[n][0] = bb.x; c2[n][1] = bb.y; c2[n][2] = bb.x; c2[n][3] = bb.y;
        }

        float hh[4][4];
        unsigned A[4];

        // MLP(angle) layer 1
#pragma unroll
        for (int n = 0; n < 4; n++) {
            const float2 bb = bfr[0][n][lane];
            hh[n][0] = bb.x; hh[n][1] = bb.y; hh[n][2] = bb.x; hh[n][3] = bb.y;
        }
#pragma unroll
        for (int n = 0; n < 4; n++) mma_bf16(hh[n], Aa0, wfrag[0 + n][lane]);
#pragma unroll
        for (int n = 0; n < 4; n++) mma_bf16(hh[n], Aa1, wfrag[4 + n][lane]);
        // relu -> layer 2 (ang_w2)
#pragma unroll
        for (int ss = 0; ss < 2; ss++) {
            A[0] = packbf(fmaxf(hh[2*ss][0], 0.f), fmaxf(hh[2*ss][1], 0.f));
            A[1] = packbf(fmaxf(hh[2*ss][2], 0.f), fmaxf(hh[2*ss][3], 0.f));
            A[2] = packbf(fmaxf(hh[2*ss+1][0], 0.f), fmaxf(hh[2*ss+1][1], 0.f));
            A[3] = packbf(fmaxf(hh[2*ss+1][2], 0.f), fmaxf(hh[2*ss+1][3], 0.f));
#pragma unroll
            for (int n = 0; n < 4; n++) mma_bf16(c2[n], A, wfrag[16 + ss * 4 + n][lane]);
        }

        // MLP(dists) layer 1
#pragma unroll
        for (int n = 0; n < 4; n++) {
            const float2 bb = bfr[1][n][lane];
            hh[n][0] = bb.x; hh[n][1] = bb.y; hh[n][2] = bb.x; hh[n][3] = bb.y;
        }
#pragma unroll
        for (int n = 0; n < 4; n++) mma_bf16(hh[n], Ad0, wfrag[8 + n][lane]);
#pragma unroll
        for (int n = 0; n < 4; n++) mma_bf16(hh[n], Ad1, wfrag[12 + n][lane]);
        // relu -> layer 2 (md_w2)
#pragma unroll
        for (int ss = 0; ss < 2; ss++) {
            A[0] = packbf(fmaxf(hh[2*ss][0], 0.f), fmaxf(hh[2*ss][1], 0.f));
            A[1] = packbf(fmaxf(hh[2*ss][2], 0.f), fmaxf(hh[2*ss][3], 0.f));
            A[2] = packbf(fmaxf(hh[2*ss+1][0], 0.f), fmaxf(hh[2*ss+1][1], 0.f));
            A[3] = packbf(fmaxf(hh[2*ss+1][2], 0.f), fmaxf(hh[2*ss+1][3], 0.f));
#pragma unroll
            for (int n = 0; n < 4; n++) mma_bf16(c2[n], A, wfrag[24 + ss * 4 + n][lane]);
        }

        // ---- add attn_bias base, store ----
#pragma unroll
        for (int n = 0; n < 4; n++) {
            float* o = outRow + (size_t)(n * 8 + tq * 2) * PLANE;
            o[j0 + 1 + qid]         = c2[n][0] + cat0;
            o[PLANE + j0 + 1 + qid] = c2[n][1] + cat0;
            o[j0 + 9 + qid]         = c2[n][2] + cat1;
            o[PLANE + j0 + 9 + qid] = c2[n][3] + cat1;
        }
    }
}

// ---------------------------------------------------------------------------
// Kernel B: border fill (row 0 and column 0): attn + virt
// ---------------------------------------------------------------------------
__global__ __launch_bounds__(256) void border_kernel(
    const float* __restrict__ attn_bias,
    const float* __restrict__ virt,
    float* __restrict__ out)
{
    const int idx = blockIdx.x * 256 + threadIdx.x;
    const int total = NG * HH * 1025;
    if (idx >= total) return;
    const int pos = idx % 1025;
    const int gh  = idx / 1025;
    const int h = gh & 31;
    const int g = gh >> 5;
    const float v = virt[h];
    float* ob = out + ((size_t)(g * HH + h)) * PLANE;
    const float* ab = attn_bias + (size_t)g * PLANE;
    if (pos < NP1) {
        ob[pos] = ab[pos] + v;                        // row 0, all j
    } else {
        const int i = pos - 512;                      // 1..512
        ob[(size_t)i * NP1] = ab[(size_t)i * NP1] + v; // col 0
    }
}

// ---------------------------------------------------------------------------
// Kernel C: edge scatter-add. One warp per edge, lane = head h.
// edge_mask is a jax bool materialized as int32 by the harness.
// ---------------------------------------------------------------------------
__global__ __launch_bounds__(256) void edge_kernel(
    const float* __restrict__ edge_feat,
    const int*   __restrict__ edge_index,
    const int*   __restrict__ edge_mask,
    const int*   __restrict__ num_ligand_atoms,
    const float* __restrict__ struct_emb,
    const float* __restrict__ plip_lig,
    const float* __restrict__ plip_prot,
    const float* __restrict__ plip_inter,
    const float* __restrict__ dist_w1, const float* __restrict__ dist_b1,
    const float* __restrict__ dist_w2, const float* __restrict__ dist_b2,
    float* __restrict__ out)
{
    __shared__ float s_w2[1024];
    __shared__ float s_w1[32], s_b1[32], s_b2[32];
    const int tid = threadIdx.x;
    for (int idx = tid; idx < 1024; idx += 256) s_w2[idx] = dist_w2[idx];
    if (tid < 32) {
        s_w1[tid] = dist_w1[tid];
        s_b1[tid] = dist_b1[tid];
        s_b2[tid] = dist_b2[tid];
    }
    __syncthreads();

    const int warp = tid >> 5;
    const int lane = tid & 31;
    const int eid = blockIdx.x * 8 + warp;     // 0 .. G*E-1 (grid exact)
    if (eid >= NG * NE) return;
    if (edge_mask[eid] == 0) return;           // masked edges contribute 0

    const int g = eid >> 13;                   // / 8192
    const int e = eid & (NE - 1);

    const float4 ef = reinterpret_cast<const float4*>(edge_feat)[eid];
    const int t0 = (int)ef.x;
    const int t1 = (int)ef.y;
    const int t2 = (int)ef.z;
    const float d = ef.w;

    const int src = edge_index[(size_t)g * 2 * NE + e];
    const int tgt = edge_index[(size_t)g * 2 * NE + NE + e];
    int nl = num_ligand_atoms[g];
    nl = nl > 1 ? nl : 1;
    const bool sl = (src > 0) && (src < nl);
    const bool tl = (tgt > 0) && (tgt < nl);

    // distance MLP: scalar -> 32 -> 32 (lane = output h)
    const float hid = fmaxf(fmaf(d, s_w1[lane], s_b1[lane]), 0.f);
    float y = s_b2[lane];
#pragma unroll
    for (int m = 0; m < 32; m++)
        y = fmaf(__shfl_sync(0xffffffffu, hid, m), s_w2[m * 32 + lane], y);

    float sel = 0.f;
    if (t0 <= 1) {
        int si = t0 * 4 + t1 * 2 + t2;
        si = si < 0 ? 0 : (si > 19 ? 19 : si);
        sel = struct_emb[si * 32 + lane];
    } else if (t0 == 5) {
        int pi = t1 < 0 ? 0 : (t1 > 14 ? 14 : t1);
        const float* tab = (sl && tl) ? plip_lig : ((!sl && !tl) ? plip_prot : plip_inter);
        sel = tab[pi * 32 + lane];
    }

    atomicAdd(out + (((size_t)(g * HH + lane)) * NP1 + (src + 1)) * NP1 + (tgt + 1), y + sel);
}

// ---------------------------------------------------------------------------
extern "C" void kernel_launch(void* const* d_in, const int* in_sizes, int n_in,
                              void* d_out, int out_size) {
    const float* edge_feat  = (const float*)d_in[0];
    const int*   edge_index = (const int*)d_in[1];
    const int*   edge_mask  = (const int*)d_in[2];
    const int*   num_lig    = (const int*)d_in[3];
    const float* attn_bias  = (const float*)d_in[4];
    const float* angle      = (const float*)d_in[5];
    const float* dists      = (const float*)d_in[6];
    // d_in[7] node_feat unused (shape only in reference)
    const float* struct_emb = (const float*)d_in[8];
    const float* plip_lig   = (const float*)d_in[9];
    const float* plip_prot  = (const float*)d_in[10];
    const float* plip_inter = (const float*)d_in[11];
    const float* dist_w1 = (const float*)d_in[12];
    const float* dist_b1 = (const float*)d_in[13];
    const float* dist_w2 = (const float*)d_in[14];
    const float* dist_b2 = (const float*)d_in[15];
    const float* ang_w1  = (const float*)d_in[16];
    const float* ang_b1  = (const float*)d_in[17];
    const float* ang_w2  = (const float*)d_in[18];
    const float* ang_b2  = (const float*)d_in[19];
    const float* md_w1   = (const float*)d_in[20];
    const float* md_b1   = (const float*)d_in[21];
    const float* md_w2   = (const float*)d_in[22];
    const float* md_b2   = (const float*)d_in[23];
    const float* virt    = (const float*)d_in[24];
    float* out = (float*)d_out;

    // interior + border overwrite the whole output (disjoint regions),
    // then edge kernel atomically adds on top (stream-ordered).
    interior_kernel<<<NG * NN, 256>>>(attn_bias, angle, dists,
                                      ang_w1, ang_b1, ang_w2, ang_b2,
                                      md_w1, md_b1, md_w2, md_b2, out);
    border_kernel<<<(NG * HH * 1025 + 255) / 256, 256>>>(attn_bias, virt, out);
    edge_kernel<<<NG * NE / 8, 256>>>(edge_feat, edge_index, edge_mask, num_lig,
                                      struct_emb, plip_lig, plip_prot, plip_inter,
                                      dist_w1, dist_b1, dist_w2, dist_b2, out);
}